// round 8
// baseline (speedup 1.0000x reference)
#include <cuda_runtime.h>
#include <cuda_bf16.h>
#include <math.h>
#include <stdint.h>

#define B_  16
#define C_  256
#define T_  2048
#define CQK_ 32
#define LOG2E_F 1.4426950408889634f

// Scratch (allocation-free rule: __device__ globals)
__device__ float g_Q[B_ * CQK_ * T_];            // [B][32][T] tf32, pre-scaled log2e
__device__ float g_K[B_ * T_ * CQK_];            // [B][T][32] transposed, tf32
__device__ __nv_bfloat16 g_V[B_ * C_ * T_];      // [B][256][T] bf16

// ===========================================================================
// helpers
// ===========================================================================
__device__ __forceinline__ uint32_t smem_u32(const void* p) {
    uint32_t a;
    asm("{ .reg .u64 t; cvta.to.shared.u64 t, %1; cvt.u32.u64 %0, t; }"
        : "=r"(a) : "l"(p));
    return a;
}
__device__ __forceinline__ float tf32_rna(float f) {
    uint32_t u;
    asm("cvt.rna.tf32.f32 %0, %1;" : "=r"(u) : "f"(f));
    return __uint_as_float(u);
}
__device__ __forceinline__ float ex2f(float x) {
    float r;
    asm("ex2.approx.f32 %0, %1;" : "=f"(r) : "f"(x));
    return r;
}
// pack: lo = b, hi = a
__device__ __forceinline__ uint32_t bf16x2_pack(float hi, float lo) {
    uint32_t r;
    asm("cvt.rn.bf16x2.f32 %0, %1, %2;" : "=r"(r) : "f"(hi), "f"(lo));
    return r;
}
__device__ __forceinline__ void mma_tf32(float d[4], const float a[4],
                                         float b0, float b1) {
    asm volatile(
        "mma.sync.aligned.m16n8k8.row.col.f32.tf32.tf32.f32 "
        "{%0,%1,%2,%3}, {%4,%5,%6,%7}, {%8,%9}, {%0,%1,%2,%3};"
        : "+f"(d[0]), "+f"(d[1]), "+f"(d[2]), "+f"(d[3])
        : "r"(__float_as_uint(a[0])), "r"(__float_as_uint(a[1])),
          "r"(__float_as_uint(a[2])), "r"(__float_as_uint(a[3])),
          "r"(__float_as_uint(b0)),  "r"(__float_as_uint(b1)));
}
__device__ __forceinline__ void mma_bf16(float d[4], uint32_t a0, uint32_t a1,
                                         uint32_t a2, uint32_t a3,
                                         uint32_t b0, uint32_t b1) {
    asm volatile(
        "mma.sync.aligned.m16n8k16.row.col.f32.bf16.bf16.f32 "
        "{%0,%1,%2,%3}, {%4,%5,%6,%7}, {%8,%9}, {%0,%1,%2,%3};"
        : "+f"(d[0]), "+f"(d[1]), "+f"(d[2]), "+f"(d[3])
        : "r"(a0), "r"(a1), "r"(a2), "r"(a3), "r"(b0), "r"(b1));
}
#define CP_ASYNC16(dst, src) \
    asm volatile("cp.async.ca.shared.global [%0], [%1], 16;" \
        :: "r"(dst), "l"(src) : "memory")
#define CP_COMMIT() asm volatile("cp.async.commit_group;" ::: "memory")
#define BAR_PAIR(id) \
    asm volatile("bar.sync %0, %1;" :: "r"(id), "r"(64) : "memory")

// ===========================================================================
// Projection (FFMA): y = (W x + b) * scale.
// mode 0: fp32 [O][T] tf32-rounded.  mode 1: fp32 [T][32] transposed, tf32.
// mode 2: bf16 [O][T].
// ===========================================================================
__global__ void __launch_bounds__(256) proj_kernel(
    const float* __restrict__ x, const float* __restrict__ W,
    const float* __restrict__ bias, void* __restrict__ yv, int O, float scale,
    int mode)
{
    __shared__ float Ws[32 * 33];
    __shared__ float xs[32 * 132];

    const int t0 = blockIdx.x * 128;
    const int o0 = blockIdx.y * 32;
    const int b  = blockIdx.z;
    const int tid = threadIdx.x;
    const int oi = tid >> 5;
    const int ti = tid & 31;

    float acc[4][4];
#pragma unroll
    for (int a = 0; a < 4; a++)
#pragma unroll
        for (int bb = 0; bb < 4; bb++) acc[a][bb] = 0.f;

    for (int k0 = 0; k0 < C_; k0 += 32) {
#pragma unroll
        for (int k = 0; k < 4; k++) {
            int idx = tid + 256 * k;
            int o = idx >> 5, c = idx & 31;
            Ws[o * 33 + c] = W[(o0 + o) * C_ + k0 + c];
        }
#pragma unroll
        for (int k = 0; k < 4; k++) {
            int f = tid + 256 * k;
            int c = f >> 5, t4 = f & 31;
            const float4 v = *(const float4*)&x[((size_t)b * C_ + (k0 + c)) * T_ + t0 + t4 * 4];
            *(float4*)&xs[c * 132 + t4 * 4] = v;
        }
        __syncthreads();

#pragma unroll 8
        for (int c = 0; c < 32; c++) {
            float w[4], xv[4];
#pragma unroll
            for (int a = 0; a < 4; a++) w[a] = Ws[(oi * 4 + a) * 33 + c];
#pragma unroll
            for (int bb = 0; bb < 4; bb++) xv[bb] = xs[c * 132 + ti + 32 * bb];
#pragma unroll
            for (int a = 0; a < 4; a++)
#pragma unroll
                for (int bb = 0; bb < 4; bb++) acc[a][bb] += w[a] * xv[bb];
        }
        __syncthreads();
    }

    if (mode == 1) {
        float* y = (float*)yv;
        float bo[4];
#pragma unroll
        for (int a = 0; a < 4; a++) bo[a] = bias[oi * 4 + a];
#pragma unroll
        for (int bb = 0; bb < 4; bb++) {
            const int t = t0 + ti + 32 * bb;
            float4 v;
            v.x = tf32_rna((acc[0][bb] + bo[0]) * scale);
            v.y = tf32_rna((acc[1][bb] + bo[1]) * scale);
            v.z = tf32_rna((acc[2][bb] + bo[2]) * scale);
            v.w = tf32_rna((acc[3][bb] + bo[3]) * scale);
            *(float4*)&y[((size_t)b * T_ + t) * 32 + oi * 4] = v;
        }
    } else if (mode == 2) {
        __nv_bfloat16* y = (__nv_bfloat16*)yv;
#pragma unroll
        for (int a = 0; a < 4; a++) {
            const int o = o0 + oi * 4 + a;
            const float bo = bias[o];
#pragma unroll
            for (int bb = 0; bb < 4; bb++) {
                const int t = t0 + ti + 32 * bb;
                y[((size_t)b * O + o) * T_ + t] = __float2bfloat16(acc[a][bb] + bo);
            }
        }
    } else {
        float* y = (float*)yv;
#pragma unroll
        for (int a = 0; a < 4; a++) {
            const int o = o0 + oi * 4 + a;
            const float bo = bias[o];
#pragma unroll
            for (int bb = 0; bb < 4; bb++) {
                const int t = t0 + ti + 32 * bb;
                y[((size_t)b * O + o) * T_ + t] = tf32_rna((acc[a][bb] + bo) * scale);
            }
        }
    }
}

// ===========================================================================
// Attention v5: MMA1 tf32 (m16n8k8), MMA2 bf16 (m16n8k16).
//  CTA = (batch, 128 t-rows). 8 warps = 4 rowgroups x 2 col-halves.
//  3-stage cp.async ring. P exchanged via bf16 smem (stride 80B).
//  k-permutation: MMA2 HW-k {2t,2t+1,2t+8,2t+9} <-> s {8t..8t+3} (+4 kstep1),
//  applied identically on A (P layout) and B (natural V order).
// ===========================================================================
#define KT_STRIDE 48                        // floats per s-row of K
#define KT_BYTES (32 * KT_STRIDE * 4)       // 6144
#define VS_STRIDE_B 80                      // bytes per c-row of V (64 used)
#define VS_BYTES (256 * VS_STRIDE_B)        // 20480
#define STAGE_BYTES (KT_BYTES + VS_BYTES)   // 26624
#define PS_OFF  (3 * STAGE_BYTES)           // 79872
#define PS_STRIDE_B 80                      // bytes per t-row of P (64 used)
#define PS_BYTES (128 * PS_STRIDE_B)        // 10240
#define LS_OFF  (PS_OFF + PS_BYTES)         // 90112
#define SMEM_BYTES (LS_OFF + 1024)          // 91136

#define MMA1_4(sdrow, aq, lo, hi) \
    mma_tf32(sdrow, aq[0], lo.x, hi.x); \
    mma_tf32(sdrow, aq[1], lo.y, hi.y); \
    mma_tf32(sdrow, aq[2], lo.z, hi.z); \
    mma_tf32(sdrow, aq[3], lo.w, hi.w);

__global__ void __launch_bounds__(256, 1) attn_mma_kernel(
    const float* __restrict__ x, float* __restrict__ out)
{
    extern __shared__ char smem[];
    const uint32_t sb = smem_u32(smem);

    const int tid = threadIdx.x;
    const int wid = tid >> 5, lid = tid & 31;
    const int g   = lid >> 2, tig = lid & 3;
    const int rg  = wid & 3;        // rowgroup 0..3 (32 rows each)
    const int ch  = wid >> 2;       // col-half 0..1
    const int b  = blockIdx.y;
    const int t0 = blockIdx.x * 128;
    const int prow = rg * 32;

    // ---- hoisted staging addresses ----
    const int krow = tid >> 3, chn8 = tid & 7;
    const uint32_t k_dst = (uint32_t)(krow * (KT_STRIDE * 4) + chn8 * 16);
    const float* kg = &g_K[(size_t)b * T_ * CQK_] + (size_t)krow * CQK_ + chn8 * 4;
    // V: thread handles c-row = tid, 4 x 16B chunks
    const uint32_t v_dst = (uint32_t)(KT_BYTES + tid * VS_STRIDE_B);
    const __nv_bfloat16* vg = &g_V[(size_t)b * C_ * T_] + (size_t)tid * T_;

    // ---- hoisted fragment byte-offsets within a stage buffer ----
    const int kf_off = ((ch * 16 + g) * KT_STRIDE + 4 * tig) * 4;       // bytes
    const int vf_off = KT_BYTES + (ch * 128 + g) * VS_STRIDE_B + 16 * tig;

    char* PsB = smem + PS_OFF;
    // P write: row (prow+g), col byte = 32*ch + 16*nbl + 4*tig
    uint32_t ps_w = (uint32_t)((prow + g) * PS_STRIDE_B + 32 * ch + 4 * tig);
    // P read: row (prow+g), byte 16*tig
    const char* ps_r = PsB + (prow + g) * PS_STRIDE_B + 16 * tig;

    // ---- rotating stage bases ----
    const char* s0 = smem;
    const char* s1 = smem + STAGE_BYTES;
    const char* s2 = smem + 2 * STAGE_BYTES;
    uint32_t u0 = sb, u1 = sb + STAGE_BYTES, u2 = sb + 2 * STAGE_BYTES;

    auto stage_to = [&](uint32_t base) {
        CP_ASYNC16(base + k_dst, kg);
        kg += 32 * CQK_;
        CP_ASYNC16(base + v_dst,      vg);
        CP_ASYNC16(base + v_dst + 16, vg + 8);
        CP_ASYNC16(base + v_dst + 32, vg + 16);
        CP_ASYNC16(base + v_dst + 48, vg + 24);
        vg += 32;
        CP_COMMIT();
    };

    stage_to(u0);
    stage_to(u1);

    // ---- Q A-fragments: 2 strips of 16 rows, permuted k (c = 4j+kb) ----
    float aQ[2][4][4];
    {
        const float* qb = &g_Q[(size_t)b * CQK_ * T_];
#pragma unroll
        for (int st = 0; st < 2; st++) {
            const int rowb = t0 + rg * 32 + st * 16;
#pragma unroll
            for (int kb = 0; kb < 4; kb++) {
                aQ[st][kb][0] = qb[(4 * tig + kb) * T_      + rowb + g];
                aQ[st][kb][1] = qb[(4 * tig + kb) * T_      + rowb + g + 8];
                aQ[st][kb][2] = qb[(4 * tig + 16 + kb) * T_ + rowb + g];
                aQ[st][kb][3] = qb[(4 * tig + 16 + kb) * T_ + rowb + g + 8];
            }
        }
    }

    float acc[2][16][4];
#pragma unroll
    for (int st = 0; st < 2; st++)
#pragma unroll
        for (int nb = 0; nb < 16; nb++)
#pragma unroll
            for (int e = 0; e < 4; e++) acc[st][nb][e] = 0.f;
    float lsum[2][2] = {{0.f, 0.f}, {0.f, 0.f}};

    const int NSTEP = T_ / 32;   // 64
    const int barid = rg + 1;

    for (int it = 0; it < NSTEP; it++) {
        if (it + 1 < NSTEP) {
            asm volatile("cp.async.wait_group 1;" ::: "memory");
        } else {
            asm volatile("cp.async.wait_group 0;" ::: "memory");
        }
        __syncthreads();   // stage(it) visible; prev-iter reads done
        if (it + 2 < NSTEP) stage_to(u2);

        // ---- MMA1 (tf32): this warp's S quarter [32 t x 16 s] ----
        const char* Kw = s0 + kf_off;
        float sd[2][2][4];
#pragma unroll
        for (int st = 0; st < 2; st++)
#pragma unroll
            for (int nbl = 0; nbl < 2; nbl++)
#pragma unroll
                for (int e = 0; e < 4; e++) sd[st][nbl][e] = 0.f;
        {
            const float4 lo0 = *(const float4*)(Kw);
            const float4 hi0 = *(const float4*)(Kw + 64);
            const float4 lo1 = *(const float4*)(Kw + 8 * KT_STRIDE * 4);
            const float4 hi1 = *(const float4*)(Kw + 8 * KT_STRIDE * 4 + 64);
            MMA1_4(sd[0][0], aQ[0], lo0, hi0);
            MMA1_4(sd[1][0], aQ[1], lo0, hi0);
            MMA1_4(sd[0][1], aQ[0], lo1, hi1);
            MMA1_4(sd[1][1], aQ[1], lo1, hi1);
        }

        // ---- P = 2^S -> bf16; lsum from the bf16-rounded values ----
#pragma unroll
        for (int st = 0; st < 2; st++) {
#pragma unroll
            for (int nbl = 0; nbl < 2; nbl++) {
                const float p0 = ex2f(sd[st][nbl][0]);
                const float p1 = ex2f(sd[st][nbl][1]);
                const float p2 = ex2f(sd[st][nbl][2]);
                const float p3 = ex2f(sd[st][nbl][3]);
                const uint32_t pk01 = bf16x2_pack(p1, p0);  // lo=p0, hi=p1
                const uint32_t pk23 = bf16x2_pack(p3, p2);
                lsum[st][0] += __uint_as_float(pk01 << 16)
                             + __uint_as_float(pk01 & 0xFFFF0000u);
                lsum[st][1] += __uint_as_float(pk23 << 16)
                             + __uint_as_float(pk23 & 0xFFFF0000u);
                const uint32_t woff = ps_w + (uint32_t)(st * 16 * PS_STRIDE_B + nbl * 16);
                *(uint32_t*)(PsB + woff)                     = pk01;
                *(uint32_t*)(PsB + woff + 8 * PS_STRIDE_B)   = pk23;
            }
        }
        BAR_PAIR(barid);    // P rows of this rowgroup complete (both halves)

        // ---- P A-frags: one LDS.128 per (strip,row-half) covers both ksteps ----
        uint4 pA[2][2];
#pragma unroll
        for (int st = 0; st < 2; st++) {
            pA[st][0] = *(const uint4*)(ps_r + st * 16 * PS_STRIDE_B);
            pA[st][1] = *(const uint4*)(ps_r + st * 16 * PS_STRIDE_B + 8 * PS_STRIDE_B);
        }

        // ---- MMA2 (bf16 m16n8k16): O[32x128] += P V^T ----
        const char* Vw = s0 + vf_off;
#pragma unroll
        for (int nb = 0; nb < 16; nb++) {
            const uint4 vq = *(const uint4*)(Vw + nb * 8 * VS_STRIDE_B);
#pragma unroll
            for (int st = 0; st < 2; st++) {
                mma_bf16(acc[st][nb], pA[st][0].x, pA[st][1].x,
                         pA[st][0].y, pA[st][1].y, vq.x, vq.y);
                mma_bf16(acc[st][nb], pA[st][0].z, pA[st][1].z,
                         pA[st][0].w, pA[st][1].w, vq.z, vq.w);
            }
        }

        // rotate ring
        const char* stmp = s0; s0 = s1; s1 = s2; s2 = stmp;
        const uint32_t utmp = u0; u0 = u1; u1 = u2; u2 = utmp;
    }

    // ---- combine partial rowsums across col-half warps ----
#pragma unroll
    for (int st = 0; st < 2; st++)
#pragma unroll
        for (int h = 0; h < 2; h++) {
            lsum[st][h] += __shfl_xor_sync(0xffffffffu, lsum[st][h], 1);
            lsum[st][h] += __shfl_xor_sync(0xffffffffu, lsum[st][h], 2);
        }
    float* LS = (float*)(smem + LS_OFF);   // [128 rows][2 halves]
    __syncthreads();
#pragma unroll
    for (int st = 0; st < 2; st++) {
        const int r0 = prow + st * 16 + g;
        LS[r0 * 2 + ch]       = lsum[st][0];
        LS[(r0 + 8) * 2 + ch] = lsum[st][1];
    }
    __syncthreads();
    float inv[2][2];
#pragma unroll
    for (int st = 0; st < 2; st++) {
        const int r0 = prow + st * 16 + g;
        inv[st][0] = 1.0f / (LS[r0 * 2] + LS[r0 * 2 + 1]);
        inv[st][1] = 1.0f / (LS[(r0 + 8) * 2] + LS[(r0 + 8) * 2 + 1]);
    }

    // ---- epilogue: smem transpose per 32-col chunk, coalesced stores ----
    float* Osm = (float*)smem;   // 32 x 132 floats
    for (int cc = 0; cc < 8; cc++) {
        __syncthreads();
        if ((cc >> 2) == ch) {
#pragma unroll
            for (int st = 0; st < 2; st++) {
                const int tl = rg * 32 + st * 16 + g;
#pragma unroll
                for (int nbl = 0; nbl < 4; nbl++) {
                    const int nb = (cc & 3) * 4 + nbl;
                    const int c0 = nbl * 8 + 2 * tig;
                    Osm[(c0 + 0) * 132 + tl]     = acc[st][nb][0] * inv[st][0];
                    Osm[(c0 + 1) * 132 + tl]     = acc[st][nb][1] * inv[st][0];
                    Osm[(c0 + 0) * 132 + tl + 8] = acc[st][nb][2] * inv[st][1];
                    Osm[(c0 + 1) * 132 + tl + 8] = acc[st][nb][3] * inv[st][1];
                }
            }
        }
        __syncthreads();
#pragma unroll
        for (int k = 0; k < 4; k++) {
            const int i = tid + k * 256;
            const int c = i >> 5;
            const int t4 = i & 31;
            float4 v = *(const float4*)&Osm[c * 132 + t4 * 4];
            const size_t gi = ((size_t)b * C_ + cc * 32 + c) * T_ + t0 + t4 * 4;
            const float4 xv = *(const float4*)&x[gi];
            v.x += xv.x; v.y += xv.y; v.z += xv.z; v.w += xv.w;
            *(float4*)&out[gi] = v;
        }
    }
}

// ===========================================================================
extern "C" void kernel_launch(void* const* d_in, const int* in_sizes, int n_in,
                              void* d_out, int out_size)
{
    const float* x  = (const float*)d_in[0];
    const float* Wq = (const float*)d_in[1];
    const float* bq = (const float*)d_in[2];
    const float* Wk = (const float*)d_in[3];
    const float* bk = (const float*)d_in[4];
    const float* Wv = (const float*)d_in[5];
    const float* bv = (const float*)d_in[6];
    float* out = (float*)d_out;

    void *qp, *kp, *vp;
    cudaGetSymbolAddress(&qp, g_Q);
    cudaGetSymbolAddress(&kp, g_K);
    cudaGetSymbolAddress(&vp, g_V);

    cudaFuncSetAttribute(attn_mma_kernel,
                         cudaFuncAttributeMaxDynamicSharedMemorySize, SMEM_BYTES);

    proj_kernel<<<dim3(T_ / 128, 1, B_), 256>>>(x, Wq, bq, qp, CQK_, LOG2E_F, 0);
    proj_kernel<<<dim3(T_ / 128, 1, B_), 256>>>(x, Wk, bk, kp, CQK_, 1.0f, 1);
    proj_kernel<<<dim3(T_ / 128, 8, B_), 256>>>(x, Wv, bv, vp, C_, 1.0f, 2);
    attn_mma_kernel<<<dim3(T_ / 128, B_), 256, SMEM_BYTES>>>(x, out);
}

// round 9
// speedup vs baseline: 1.3933x; 1.3933x over previous
#include <cuda_runtime.h>
#include <cuda_bf16.h>
#include <math.h>
#include <stdint.h>

#define B_  16
#define C_  256
#define T_  2048
#define CQK_ 32
#define LOG2E_F 1.4426950408889634f

// Scratch (allocation-free rule: __device__ globals)
__device__ float g_Q[B_ * CQK_ * T_];            // [B][32][T] tf32, pre-scaled log2e
__device__ float g_K[B_ * T_ * CQK_];            // [B][T][32] transposed, tf32
__device__ __nv_bfloat16 g_V[B_ * C_ * T_];      // [B][256][T] bf16

// ===========================================================================
// helpers
// ===========================================================================
__device__ __forceinline__ uint32_t smem_u32(const void* p) {
    uint32_t a;
    asm("{ .reg .u64 t; cvta.to.shared.u64 t, %1; cvt.u32.u64 %0, t; }"
        : "=r"(a) : "l"(p));
    return a;
}
__device__ __forceinline__ float tf32_rna(float f) {
    uint32_t u;
    asm("cvt.rna.tf32.f32 %0, %1;" : "=r"(u) : "f"(f));
    return __uint_as_float(u);
}
__device__ __forceinline__ float ex2f(float x) {
    float r;
    asm("ex2.approx.f32 %0, %1;" : "=f"(r) : "f"(x));
    return r;
}
// pack: lo = b, hi = a
__device__ __forceinline__ uint32_t bf16x2_pack(float hi, float lo) {
    uint32_t r;
    asm("cvt.rn.bf16x2.f32 %0, %1, %2;" : "=r"(r) : "f"(hi), "f"(lo));
    return r;
}
__device__ __forceinline__ void mma_tf32(float d[4], const float a[4],
                                         float b0, float b1) {
    asm volatile(
        "mma.sync.aligned.m16n8k8.row.col.f32.tf32.tf32.f32 "
        "{%0,%1,%2,%3}, {%4,%5,%6,%7}, {%8,%9}, {%0,%1,%2,%3};"
        : "+f"(d[0]), "+f"(d[1]), "+f"(d[2]), "+f"(d[3])
        : "r"(__float_as_uint(a[0])), "r"(__float_as_uint(a[1])),
          "r"(__float_as_uint(a[2])), "r"(__float_as_uint(a[3])),
          "r"(__float_as_uint(b0)),  "r"(__float_as_uint(b1)));
}
__device__ __forceinline__ void mma_bf16(float d[4], uint32_t a0, uint32_t a1,
                                         uint32_t a2, uint32_t a3,
                                         uint32_t b0, uint32_t b1) {
    asm volatile(
        "mma.sync.aligned.m16n8k16.row.col.f32.bf16.bf16.f32 "
        "{%0,%1,%2,%3}, {%4,%5,%6,%7}, {%8,%9}, {%0,%1,%2,%3};"
        : "+f"(d[0]), "+f"(d[1]), "+f"(d[2]), "+f"(d[3])
        : "r"(a0), "r"(a1), "r"(a2), "r"(a3), "r"(b0), "r"(b1));
}
#define CP_ASYNC16(dst, src) \
    asm volatile("cp.async.ca.shared.global [%0], [%1], 16;" \
        :: "r"(dst), "l"(src) : "memory")
#define CP_COMMIT() asm volatile("cp.async.commit_group;" ::: "memory")
#define BAR_PAIR(id) \
    asm volatile("bar.sync %0, %1;" :: "r"(id), "r"(64) : "memory")

// ===========================================================================
// Projection (FFMA): y = (W x + b) * scale.
// mode 0: fp32 [O][T] tf32-rounded.  mode 1: fp32 [T][32] transposed, tf32.
// mode 2: bf16 [O][T].
// ===========================================================================
__global__ void __launch_bounds__(256) proj_kernel(
    const float* __restrict__ x, const float* __restrict__ W,
    const float* __restrict__ bias, void* __restrict__ yv, int O, float scale,
    int mode)
{
    __shared__ float Ws[32 * 33];
    __shared__ float xs[32 * 132];

    const int t0 = blockIdx.x * 128;
    const int o0 = blockIdx.y * 32;
    const int b  = blockIdx.z;
    const int tid = threadIdx.x;
    const int oi = tid >> 5;
    const int ti = tid & 31;

    float acc[4][4];
#pragma unroll
    for (int a = 0; a < 4; a++)
#pragma unroll
        for (int bb = 0; bb < 4; bb++) acc[a][bb] = 0.f;

    for (int k0 = 0; k0 < C_; k0 += 32) {
#pragma unroll
        for (int k = 0; k < 4; k++) {
            int idx = tid + 256 * k;
            int o = idx >> 5, c = idx & 31;
            Ws[o * 33 + c] = W[(o0 + o) * C_ + k0 + c];
        }
#pragma unroll
        for (int k = 0; k < 4; k++) {
            int f = tid + 256 * k;
            int c = f >> 5, t4 = f & 31;
            const float4 v = *(const float4*)&x[((size_t)b * C_ + (k0 + c)) * T_ + t0 + t4 * 4];
            *(float4*)&xs[c * 132 + t4 * 4] = v;
        }
        __syncthreads();

#pragma unroll 8
        for (int c = 0; c < 32; c++) {
            float w[4], xv[4];
#pragma unroll
            for (int a = 0; a < 4; a++) w[a] = Ws[(oi * 4 + a) * 33 + c];
#pragma unroll
            for (int bb = 0; bb < 4; bb++) xv[bb] = xs[c * 132 + ti + 32 * bb];
#pragma unroll
            for (int a = 0; a < 4; a++)
#pragma unroll
                for (int bb = 0; bb < 4; bb++) acc[a][bb] += w[a] * xv[bb];
        }
        __syncthreads();
    }

    if (mode == 1) {
        float* y = (float*)yv;
        float bo[4];
#pragma unroll
        for (int a = 0; a < 4; a++) bo[a] = bias[oi * 4 + a];
#pragma unroll
        for (int bb = 0; bb < 4; bb++) {
            const int t = t0 + ti + 32 * bb;
            float4 v;
            v.x = tf32_rna((acc[0][bb] + bo[0]) * scale);
            v.y = tf32_rna((acc[1][bb] + bo[1]) * scale);
            v.z = tf32_rna((acc[2][bb] + bo[2]) * scale);
            v.w = tf32_rna((acc[3][bb] + bo[3]) * scale);
            *(float4*)&y[((size_t)b * T_ + t) * 32 + oi * 4] = v;
        }
    } else if (mode == 2) {
        __nv_bfloat16* y = (__nv_bfloat16*)yv;
#pragma unroll
        for (int a = 0; a < 4; a++) {
            const int o = o0 + oi * 4 + a;
            const float bo = bias[o];
#pragma unroll
            for (int bb = 0; bb < 4; bb++) {
                const int t = t0 + ti + 32 * bb;
                y[((size_t)b * O + o) * T_ + t] = __float2bfloat16(acc[a][bb] + bo);
            }
        }
    } else {
        float* y = (float*)yv;
#pragma unroll
        for (int a = 0; a < 4; a++) {
            const int o = o0 + oi * 4 + a;
            const float bo = bias[o];
#pragma unroll
            for (int bb = 0; bb < 4; bb++) {
                const int t = t0 + ti + 32 * bb;
                y[((size_t)b * O + o) * T_ + t] = tf32_rna((acc[a][bb] + bo) * scale);
            }
        }
    }
}

// ===========================================================================
// Attention v6: 512 threads, 16 warps = 8 rowgroups(16 rows) x 2 col-halves.
//  MMA1 tf32 m16n8k8, MMA2 bf16 m16n8k16 (k-permuted, LDS.128 fragments).
//  3-stage cp.async ring, pointer rotation, 1 CTA + 1 paired barrier / iter.
// ===========================================================================
#define KT_STRIDE 48                        // floats per s-row of K
#define KT_BYTES (32 * KT_STRIDE * 4)       // 6144
#define VS_STRIDE_B 80                      // bytes per c-row of V (64 used)
#define VS_BYTES (256 * VS_STRIDE_B)        // 20480
#define STAGE_BYTES (KT_BYTES + VS_BYTES)   // 26624
#define PS_OFF  (3 * STAGE_BYTES)           // 79872
#define PS_STRIDE_B 80                      // bytes per t-row of P (64 used)
#define PS_BYTES (128 * PS_STRIDE_B)        // 10240
#define LS_OFF  (PS_OFF + PS_BYTES)         // 90112
#define SMEM_BYTES (LS_OFF + 1024)          // 91136

#define MMA1_4(sdrow, aq, lo, hi) \
    mma_tf32(sdrow, aq[0], lo.x, hi.x); \
    mma_tf32(sdrow, aq[1], lo.y, hi.y); \
    mma_tf32(sdrow, aq[2], lo.z, hi.z); \
    mma_tf32(sdrow, aq[3], lo.w, hi.w);

__global__ void __launch_bounds__(512, 1) attn_mma_kernel(
    const float* __restrict__ x, float* __restrict__ out)
{
    extern __shared__ char smem[];
    const uint32_t sb = smem_u32(smem);

    const int tid = threadIdx.x;
    const int wid = tid >> 5, lid = tid & 31;
    const int g   = lid >> 2, tig = lid & 3;
    const int rg  = wid & 7;        // rowgroup 0..7 (16 rows each)
    const int ch  = wid >> 3;       // col-half 0..1
    const int b  = blockIdx.y;
    const int t0 = blockIdx.x * 128;
    const int prow = rg * 16;

    // ---- hoisted staging addresses ----
    // K: threads 0..255, one 16B chunk each
    const int krow = (tid & 255) >> 3, chn8 = tid & 7;
    const uint32_t k_dst = (uint32_t)(krow * (KT_STRIDE * 4) + chn8 * 16);
    const float* kg = &g_K[(size_t)b * T_ * CQK_] + (size_t)krow * CQK_ + chn8 * 4;
    // V: c-row = tid>>1, half = tid&1, two 16B chunks each
    const int vrow = tid >> 1, vhalf = tid & 1;
    const uint32_t v_dst = (uint32_t)(KT_BYTES + vrow * VS_STRIDE_B + vhalf * 32);
    const __nv_bfloat16* vg = &g_V[(size_t)b * C_ * T_] + (size_t)vrow * T_ + vhalf * 16;

    // ---- hoisted fragment byte-offsets within a stage buffer ----
    const int kf_off = ((ch * 16 + g) * KT_STRIDE + 4 * tig) * 4;       // bytes
    const int vf_off = KT_BYTES + (ch * 128 + g) * VS_STRIDE_B + 16 * tig;

    char* PsB = smem + PS_OFF;
    const uint32_t ps_w = (uint32_t)((prow + g) * PS_STRIDE_B + 32 * ch + 4 * tig);
    const char* ps_r = PsB + (prow + g) * PS_STRIDE_B + 16 * tig;

    // ---- rotating stage bases ----
    const char* s0 = smem;
    const char* s1 = smem + STAGE_BYTES;
    const char* s2 = smem + 2 * STAGE_BYTES;
    uint32_t u0 = sb, u1 = sb + STAGE_BYTES, u2 = sb + 2 * STAGE_BYTES;

    auto stage_to = [&](uint32_t base) {
        if (tid < 256) CP_ASYNC16(base + k_dst, kg);
        kg += 32 * CQK_;
        CP_ASYNC16(base + v_dst,      vg);
        CP_ASYNC16(base + v_dst + 16, vg + 8);
        vg += 32;
        CP_COMMIT();
    };

    stage_to(u0);
    stage_to(u1);

    // ---- Q A-fragments: 1 strip of 16 rows, permuted k (c = 4j+kb) ----
    float aQ[4][4];
    {
        const float* qb = &g_Q[(size_t)b * CQK_ * T_];
        const int rowb = t0 + prow;
#pragma unroll
        for (int kb = 0; kb < 4; kb++) {
            aQ[kb][0] = qb[(4 * tig + kb) * T_      + rowb + g];
            aQ[kb][1] = qb[(4 * tig + kb) * T_      + rowb + g + 8];
            aQ[kb][2] = qb[(4 * tig + 16 + kb) * T_ + rowb + g];
            aQ[kb][3] = qb[(4 * tig + 16 + kb) * T_ + rowb + g + 8];
        }
    }

    float acc[16][4];
#pragma unroll
    for (int nb = 0; nb < 16; nb++)
#pragma unroll
        for (int e = 0; e < 4; e++) acc[nb][e] = 0.f;
    float lsum0 = 0.f, lsum1 = 0.f;

    const int NSTEP = T_ / 32;   // 64
    const int barid = rg + 1;    // named barriers 1..8, 64 threads each

    for (int it = 0; it < NSTEP; it++) {
        if (it + 1 < NSTEP) {
            asm volatile("cp.async.wait_group 1;" ::: "memory");
        } else {
            asm volatile("cp.async.wait_group 0;" ::: "memory");
        }
        __syncthreads();   // stage(it) visible; prev-iter reads done
        if (it + 2 < NSTEP) stage_to(u2);

        // ---- MMA1 (tf32): this warp's S quarter [16 t x 16 s] ----
        const char* Kw = s0 + kf_off;
        float sd[2][4];
#pragma unroll
        for (int nbl = 0; nbl < 2; nbl++)
#pragma unroll
            for (int e = 0; e < 4; e++) sd[nbl][e] = 0.f;
        {
            const float4 lo0 = *(const float4*)(Kw);
            const float4 hi0 = *(const float4*)(Kw + 64);
            const float4 lo1 = *(const float4*)(Kw + 8 * KT_STRIDE * 4);
            const float4 hi1 = *(const float4*)(Kw + 8 * KT_STRIDE * 4 + 64);
            MMA1_4(sd[0], aQ, lo0, hi0);
            MMA1_4(sd[1], aQ, lo1, hi1);
        }

        // ---- P = 2^S -> bf16; lsum from the bf16-rounded values ----
#pragma unroll
        for (int nbl = 0; nbl < 2; nbl++) {
            const float p0 = ex2f(sd[nbl][0]);
            const float p1 = ex2f(sd[nbl][1]);
            const float p2 = ex2f(sd[nbl][2]);
            const float p3 = ex2f(sd[nbl][3]);
            const uint32_t pk01 = bf16x2_pack(p1, p0);  // lo=p0, hi=p1
            const uint32_t pk23 = bf16x2_pack(p3, p2);
            lsum0 += __uint_as_float(pk01 << 16)
                   + __uint_as_float(pk01 & 0xFFFF0000u);
            lsum1 += __uint_as_float(pk23 << 16)
                   + __uint_as_float(pk23 & 0xFFFF0000u);
            const uint32_t woff = ps_w + (uint32_t)(nbl * 16);
            *(uint32_t*)(PsB + woff)                   = pk01;
            *(uint32_t*)(PsB + woff + 8 * PS_STRIDE_B) = pk23;
        }
        BAR_PAIR(barid);    // P rows of this rowgroup complete (both halves)

        // ---- P A-frags: one LDS.128 per row-half covers both ksteps ----
        const uint4 pA0 = *(const uint4*)(ps_r);
        const uint4 pA1 = *(const uint4*)(ps_r + 8 * PS_STRIDE_B);

        // ---- MMA2 (bf16 m16n8k16): O[16x128] += P V^T ----
        const char* Vw = s0 + vf_off;
#pragma unroll
        for (int nb = 0; nb < 16; nb++) {
            const uint4 vq = *(const uint4*)(Vw + nb * 8 * VS_STRIDE_B);
            mma_bf16(acc[nb], pA0.x, pA1.x, pA0.y, pA1.y, vq.x, vq.y);
            mma_bf16(acc[nb], pA0.z, pA1.z, pA0.w, pA1.w, vq.z, vq.w);
        }

        // rotate ring
        const char* stmp = s0; s0 = s1; s1 = s2; s2 = stmp;
        const uint32_t utmp = u0; u0 = u1; u1 = u2; u2 = utmp;
    }

    // ---- combine partial rowsums: quad-reduce, then across col-halves ----
    lsum0 += __shfl_xor_sync(0xffffffffu, lsum0, 1);
    lsum0 += __shfl_xor_sync(0xffffffffu, lsum0, 2);
    lsum1 += __shfl_xor_sync(0xffffffffu, lsum1, 1);
    lsum1 += __shfl_xor_sync(0xffffffffu, lsum1, 2);
    float* LS = (float*)(smem + LS_OFF);   // [128 rows][2 halves]
    __syncthreads();
    LS[(prow + g) * 2 + ch]     = lsum0;
    LS[(prow + 8 + g) * 2 + ch] = lsum1;
    __syncthreads();
    const float inv0 = 1.0f / (LS[(prow + g) * 2]     + LS[(prow + g) * 2 + 1]);
    const float inv1 = 1.0f / (LS[(prow + 8 + g) * 2] + LS[(prow + 8 + g) * 2 + 1]);

    // ---- epilogue: smem transpose per 32-col chunk, coalesced stores ----
    float* Osm = (float*)smem;   // 32 x 132 floats
    const int tl = prow + g;
    for (int cc = 0; cc < 8; cc++) {
        __syncthreads();
        if ((cc >> 2) == ch) {
#pragma unroll
            for (int nbl = 0; nbl < 4; nbl++) {
                const int nb = (cc & 3) * 4 + nbl;
                const int c0 = nbl * 8 + 2 * tig;
                Osm[(c0 + 0) * 132 + tl]     = acc[nb][0] * inv0;
                Osm[(c0 + 1) * 132 + tl]     = acc[nb][1] * inv0;
                Osm[(c0 + 0) * 132 + tl + 8] = acc[nb][2] * inv1;
                Osm[(c0 + 1) * 132 + tl + 8] = acc[nb][3] * inv1;
            }
        }
        __syncthreads();
#pragma unroll
        for (int k = 0; k < 2; k++) {
            const int i = tid + k * 512;
            const int c = i >> 5;
            const int t4 = i & 31;
            float4 v = *(const float4*)&Osm[c * 132 + t4 * 4];
            const size_t gi = ((size_t)b * C_ + cc * 32 + c) * T_ + t0 + t4 * 4;
            const float4 xv = *(const float4*)&x[gi];
            v.x += xv.x; v.y += xv.y; v.z += xv.z; v.w += xv.w;
            *(float4*)&out[gi] = v;
        }
    }
}

// ===========================================================================
extern "C" void kernel_launch(void* const* d_in, const int* in_sizes, int n_in,
                              void* d_out, int out_size)
{
    const float* x  = (const float*)d_in[0];
    const float* Wq = (const float*)d_in[1];
    const float* bq = (const float*)d_in[2];
    const float* Wk = (const float*)d_in[3];
    const float* bk = (const float*)d_in[4];
    const float* Wv = (const float*)d_in[5];
    const float* bv = (const float*)d_in[6];
    float* out = (float*)d_out;

    void *qp, *kp, *vp;
    cudaGetSymbolAddress(&qp, g_Q);
    cudaGetSymbolAddress(&kp, g_K);
    cudaGetSymbolAddress(&vp, g_V);

    cudaFuncSetAttribute(attn_mma_kernel,
                         cudaFuncAttributeMaxDynamicSharedMemorySize, SMEM_BYTES);

    proj_kernel<<<dim3(T_ / 128, 1, B_), 256>>>(x, Wq, bq, qp, CQK_, LOG2E_F, 0);
    proj_kernel<<<dim3(T_ / 128, 1, B_), 256>>>(x, Wk, bk, kp, CQK_, 1.0f, 1);
    proj_kernel<<<dim3(T_ / 128, 8, B_), 256>>>(x, Wv, bv, vp, C_, 1.0f, 2);
    attn_mma_kernel<<<dim3(T_ / 128, B_), 512, SMEM_BYTES>>>(x, out);
}